// round 1
// baseline (speedup 1.0000x reference)
#include <cuda_runtime.h>

// ---------------- problem constants ----------------
#define B_    4
#define CIN   256
#define H_    56
#define W_    56
#define HW    3136          // 56*56, = 49*64
#define REL   16
#define OUT_  256
#define SP_   8
#define WS_   32
#define KK    7
#define K2    49
#define PAD_  3
#define MPROJ 288           // 16 (x1) + 16 (x2) + 256 (x3)

// ---------------- scratch (device globals; no allocations allowed) --------
__device__ float g_wc[MPROJ * CIN];          // packed projection weights
__device__ float g_bc[MPROJ];                // packed projection bias
__device__ float g_proj[B_ * MPROJ * HW];    // [b][row][p]: rows 0-15 x1, 16-31 x2, 32-287 x3
__device__ float g_w[B_ * WS_ * HW * K2];    // softmaxed attn weights [b][g][p][k] (k contiguous)
__device__ float g_agg[B_ * OUT_ * HW];      // aggregated values [b][c][p], c = g*8+s

__device__ __forceinline__ int refl(int i, int n) {
    if (i < 0) i = -i;
    if (i >= n) i = 2 * n - 2 - i;
    return i;
}

// ---------------- kernel 0: pack projection weights -----------------------
__global__ void pack_kernel(const float* __restrict__ w1, const float* __restrict__ b1,
                            const float* __restrict__ w2, const float* __restrict__ b2,
                            const float* __restrict__ w3, const float* __restrict__ b3) {
    int i = blockIdx.x * blockDim.x + threadIdx.x;
    if (i < MPROJ * CIN) {
        int r = i / CIN, c = i % CIN;
        float v;
        if (r < 16)      v = w1[r * CIN + c];
        else if (r < 32) v = w2[(r - 16) * CIN + c];
        else             v = w3[(r - 32) * CIN + c];
        g_wc[i] = v;
    }
    if (i < MPROJ) {
        g_bc[i] = (i < 16) ? b1[i] : ((i < 32) ? b2[i - 16] : b3[i - 32]);
    }
}

// ---------------- kernel 1: projection GEMM -------------------------------
// C[b][m][n] = sum_k g_wc[m][k] * x[b][k][n] + g_bc[m]
// BM=96 (288 = 3*96, no predication), BN=64 (3136 = 49*64), BK=16, 256 thr.
#define BM 96
#define BN 64
#define BK 16
__global__ __launch_bounds__(256) void proj_gemm(const float* __restrict__ x) {
    __shared__ float As[BK][BM + 1];   // +1 pad: avoid 16-way STS conflicts (96 % 32 == 0)
    __shared__ float Bs[BK][BN];

    int b  = blockIdx.z;
    int m0 = blockIdx.y * BM;
    int n0 = blockIdx.x * BN;
    int t  = threadIdx.x;
    int tx = t & 15;        // 0..15 -> 4 cols each
    int ty = t >> 4;        // 0..15 -> 6 rows each

    const float* xb = x + (size_t)b * CIN * HW;

    float acc[6][4];
#pragma unroll
    for (int i = 0; i < 6; i++)
#pragma unroll
        for (int j = 0; j < 4; j++) acc[i][j] = 0.0f;

    for (int k0 = 0; k0 < CIN; k0 += BK) {
        // load A tile (96x16), store transposed As[k][m]
#pragma unroll
        for (int q = 0; q < 6; q++) {
            int idx = t + q * 256;
            int col = idx & 15;
            int row = idx >> 4;
            As[col][row] = g_wc[(m0 + row) * CIN + k0 + col];
        }
        // load B tile (16x64) vectorized
        {
            int row = t >> 4, cg = t & 15;
            float4 v = *reinterpret_cast<const float4*>(&xb[(size_t)(k0 + row) * HW + n0 + cg * 4]);
            *reinterpret_cast<float4*>(&Bs[row][cg * 4]) = v;
        }
        __syncthreads();
#pragma unroll
        for (int k = 0; k < BK; k++) {
            float a[6];
#pragma unroll
            for (int i = 0; i < 6; i++) a[i] = As[k][ty * 6 + i];
            float4 bv = *reinterpret_cast<float4*>(&Bs[k][tx * 4]);
            float bb[4] = {bv.x, bv.y, bv.z, bv.w};
#pragma unroll
            for (int i = 0; i < 6; i++)
#pragma unroll
                for (int j = 0; j < 4; j++) acc[i][j] = fmaf(a[i], bb[j], acc[i][j]);
        }
        __syncthreads();
    }
#pragma unroll
    for (int i = 0; i < 6; i++) {
        int m = m0 + ty * 6 + i;
        float bias = g_bc[m];
        float4 v = make_float4(acc[i][0] + bias, acc[i][1] + bias,
                               acc[i][2] + bias, acc[i][3] + bias);
        *reinterpret_cast<float4*>(&g_proj[((size_t)b * MPROJ + m) * HW + n0 + tx * 4]) = v;
    }
}

// ---------------- kernel 2: attention weights + softmax -------------------
// 128 threads = 4 warps; one warp per pixel; lane = tap (2 iters for 49 taps).
__global__ __launch_bounds__(128) void attn_kernel(
    const float* __restrict__ bn1g, const float* __restrict__ bn1b,
    const float* __restrict__ bn1m, const float* __restrict__ bn1v,
    const float* __restrict__ cw1,
    const float* __restrict__ bn2g, const float* __restrict__ bn2b,
    const float* __restrict__ bn2m, const float* __restrict__ bn2v,
    const float* __restrict__ cw2, const float* __restrict__ cb) {

    __shared__ float s_logit[4][32][49];
    __shared__ float s1[16], t1[16], s2[16], t2[16];
    __shared__ float scw1[16 * 16];  // [o][c]
    __shared__ float scw2[32 * 16];  // [g][o]
    __shared__ float scb[32];
    __shared__ float smax[4][32], sinv[4][32];

    int t = threadIdx.x;
    if (t < 16) {
        float s = bn1g[t] * rsqrtf(bn1v[t] + 1e-5f);
        s1[t] = s; t1[t] = bn1b[t] - s * bn1m[t];
        float ss = bn2g[t] * rsqrtf(bn2v[t] + 1e-5f);
        s2[t] = ss; t2[t] = bn2b[t] - ss * bn2m[t];
    }
    for (int i = t; i < 256; i += 128) scw1[i] = cw1[i];
    for (int i = t; i < 512; i += 128) scw2[i] = cw2[i];
    if (t < 32) scb[t] = cb[t];
    __syncthreads();

    int warp = t >> 5, lane = t & 31;
    int gp = blockIdx.x * 4 + warp;       // global pixel index (b*HW + p)
    int b = gp / HW, p = gp % HW;
    int h = p / W_, w = p % W_;

    const float* base = g_proj + (size_t)b * MPROJ * HW;
    float x1v[16];
#pragma unroll
    for (int c = 0; c < 16; c++) x1v[c] = base[c * HW + p];
    const float* x2b = base + 16 * HW;

#pragma unroll
    for (int it = 0; it < 2; it++) {
        int k = lane + it * 32;
        if (k < 49) {
            int dy = k / 7 - 3, dx = k % 7 - 3;
            int pn = refl(h + dy, H_) * W_ + refl(w + dx, W_);
            float h1[16];
#pragma unroll
            for (int o = 0; o < 16; o++) h1[o] = 0.0f;
#pragma unroll
            for (int c = 0; c < 16; c++) {
                float d = x1v[c] - x2b[c * HW + pn];
                float a = fmaxf(fmaf(s1[c], d, t1[c]), 0.0f);
#pragma unroll
                for (int o = 0; o < 16; o++) h1[o] = fmaf(scw1[o * 16 + c], a, h1[o]);
            }
            float h2[32];
#pragma unroll
            for (int g = 0; g < 32; g++) h2[g] = scb[g];
#pragma unroll
            for (int o = 0; o < 16; o++) {
                float a = fmaxf(fmaf(s2[o], h1[o], t2[o]), 0.0f);
#pragma unroll
                for (int g = 0; g < 32; g++) h2[g] = fmaf(scw2[g * 16 + o], a, h2[g]);
            }
#pragma unroll
            for (int g = 0; g < 32; g++) s_logit[warp][g][k] = h2[g];
        }
    }
    __syncthreads();

    // softmax stats: thread -> (pix, g)
    {
        int pix = t >> 5, g = t & 31;
        float m = -1e30f;
#pragma unroll
        for (int k = 0; k < 49; k++) m = fmaxf(m, s_logit[pix][g][k]);
        float s = 0.0f;
#pragma unroll
        for (int k = 0; k < 49; k++) s += __expf(s_logit[pix][g][k] - m);
        smax[pix][g] = m;
        sinv[pix][g] = 1.0f / s;
    }
    __syncthreads();

    // coalesced write: g_w[b][g][p][k], k fastest within (g,pix)
    for (int flat = t; flat < 4 * 32 * 49; flat += 128) {
        int k = flat % 49;
        int gpg = flat / 49;
        int pix = gpg & 3;
        int g = gpg >> 2;
        int gpix = blockIdx.x * 4 + pix;
        int bb = gpix / HW, pp = gpix % HW;
        float v = __expf(s_logit[pix][g][k] - smax[pix][g]) * sinv[pix][g];
        g_w[(((size_t)bb * WS_ + g) * HW + pp) * K2 + k] = v;
    }
}

// ---------------- kernel 3: aggregation -----------------------------------
// grid (49 p-chunks, 32 g, 4 b); 256 threads = 64 pixels x 4 s-slices.
__global__ __launch_bounds__(256) void agg_kernel() {
    __shared__ float sw[64 * 49];  // [p_local][k]

    int b = blockIdx.z, g = blockIdx.y, p0 = blockIdx.x * 64;
    int t = threadIdx.x;

    const float* wp = g_w + (((size_t)b * WS_ + g) * HW + p0) * K2;
    for (int i = t; i < 64 * 49 / 4; i += 256)
        reinterpret_cast<float4*>(sw)[i] = reinterpret_cast<const float4*>(wp)[i];
    __syncthreads();

    int pl = t & 63, sq = t >> 6;
    int p = p0 + pl;
    int h = p / W_, w = p % W_;
    int hn[7], wn[7];
#pragma unroll
    for (int i = 0; i < 7; i++) {
        hn[i] = refl(h + i - 3, H_) * W_;
        wn[i] = refl(w + i - 3, W_);
    }
    const float* x3base = g_proj + ((size_t)b * MPROJ + 32) * HW;
    const float* wsm = sw + pl * 49;

#pragma unroll
    for (int si = 0; si < 2; si++) {
        int s = sq + si * 4;
        int c = g * 8 + s;
        const float* x3 = x3base + (size_t)c * HW;
        float acc = 0.0f;
#pragma unroll
        for (int i = 0; i < 7; i++)
#pragma unroll
            for (int j = 0; j < 7; j++)
                acc = fmaf(x3[hn[i] + wn[j]], wsm[i * 7 + j], acc);
        g_agg[((size_t)b * OUT_ + c) * HW + p] = acc;
    }
}

// ---------------- kernel 4: position2 grouped conv ------------------------
// out[b][g*8+o][p] = sum_s agg[s*32+g]*pw[g][o][s] + sum_k w[g][k]*pw[g][o][8+k]
__global__ __launch_bounds__(256) void pos2_kernel(const float* __restrict__ pos2w,
                                                   float* __restrict__ out) {
    __shared__ float sw[64 * 49];
    __shared__ float sxv[8][64];
    __shared__ float spw[8 * 57];

    int b = blockIdx.z, g = blockIdx.y, p0 = blockIdx.x * 64;
    int t = threadIdx.x;

    const float* wp = g_w + (((size_t)b * WS_ + g) * HW + p0) * K2;
    for (int i = t; i < 64 * 49 / 4; i += 256)
        reinterpret_cast<float4*>(sw)[i] = reinterpret_cast<const float4*>(wp)[i];
    for (int i = t; i < 8 * 57; i += 256) spw[i] = pos2w[g * 8 * 57 + i];
    for (int i = t; i < 512; i += 256) {
        int s = i >> 6, pl = i & 63;
        sxv[s][pl] = g_agg[((size_t)b * OUT_ + s * 32 + g) * HW + p0 + pl];
    }
    __syncthreads();

    int pl = t & 63, oq = t >> 6;
    const float* wsm = sw + pl * 49;
#pragma unroll
    for (int oi = 0; oi < 2; oi++) {
        int o = oq + oi * 4;
        float acc = 0.0f;
#pragma unroll
        for (int s = 0; s < 8; s++) acc = fmaf(sxv[s][pl], spw[o * 57 + s], acc);
#pragma unroll
        for (int k = 0; k < 49; k++) acc = fmaf(wsm[k], spw[o * 57 + 8 + k], acc);
        out[((size_t)b * OUT_ + g * 8 + o) * HW + p0 + pl] = acc;
    }
}

// ---------------- launch ---------------------------------------------------
extern "C" void kernel_launch(void* const* d_in, const int* in_sizes, int n_in,
                              void* d_out, int out_size) {
    const float* x    = (const float*)d_in[0];
    const float* w1   = (const float*)d_in[1];
    const float* b1   = (const float*)d_in[2];
    const float* w2   = (const float*)d_in[3];
    const float* b2   = (const float*)d_in[4];
    const float* w3   = (const float*)d_in[5];
    const float* b3   = (const float*)d_in[6];
    const float* bn1g = (const float*)d_in[7];
    const float* bn1b = (const float*)d_in[8];
    const float* bn1m = (const float*)d_in[9];
    const float* bn1v = (const float*)d_in[10];
    const float* cw1  = (const float*)d_in[11];
    const float* bn2g = (const float*)d_in[12];
    const float* bn2b = (const float*)d_in[13];
    const float* bn2m = (const float*)d_in[14];
    const float* bn2v = (const float*)d_in[15];
    const float* cw2  = (const float*)d_in[16];
    const float* cb   = (const float*)d_in[17];
    const float* p2w  = (const float*)d_in[18];
    float* out = (float*)d_out;

    pack_kernel<<<(MPROJ * CIN + 255) / 256, 256>>>(w1, b1, w2, b2, w3, b3);

    dim3 gg(HW / BN, MPROJ / BM, B_);   // 49 x 3 x 4
    proj_gemm<<<gg, 256>>>(x);

    attn_kernel<<<(B_ * HW) / 4, 128>>>(bn1g, bn1b, bn1m, bn1v, cw1,
                                        bn2g, bn2b, bn2m, bn2v, cw2, cb);

    dim3 ga(HW / 64, WS_, B_);          // 49 x 32 x 4
    agg_kernel<<<ga, 256>>>();
    pos2_kernel<<<ga, 256>>>(p2w, out);
}

// round 2
// speedup vs baseline: 2.9707x; 2.9707x over previous
#include <cuda_runtime.h>

// ---------------- problem constants ----------------
#define B_    4
#define CIN   256
#define H_    56
#define W_    56
#define HW    3136          // 56*56
#define REL   16
#define OUT_  256
#define SP_   8
#define WS_   32
#define K2    49
#define MPROJ 288           // 16 (x1) + 16 (x2) + 256 (x3)

// ---------------- scratch (device globals) --------------------------------
__device__ float g_wc[MPROJ * CIN];
__device__ float g_bc[MPROJ];
__device__ float g_proj[B_ * MPROJ * HW];    // rows 0-15 x1, 16-31 x2, 32-287 x3
__device__ float g_w[B_ * WS_ * HW * K2];    // [b][g][p][k]
__device__ float g_agg[B_ * OUT_ * HW];      // [b][c][p], c = g*8+s

__device__ __forceinline__ int refl(int i, int n) {
    if (i < 0) i = -i;
    if (i >= n) i = 2 * n - 2 - i;
    return i;
}

// ---------------- kernel 0: pack projection weights -----------------------
__global__ void pack_kernel(const float* __restrict__ w1, const float* __restrict__ b1,
                            const float* __restrict__ w2, const float* __restrict__ b2,
                            const float* __restrict__ w3, const float* __restrict__ b3) {
    int i = blockIdx.x * blockDim.x + threadIdx.x;
    if (i < MPROJ * CIN) {
        int r = i / CIN, c = i % CIN;
        float v;
        if (r < 16)      v = w1[r * CIN + c];
        else if (r < 32) v = w2[(r - 16) * CIN + c];
        else             v = w3[(r - 32) * CIN + c];
        g_wc[i] = v;
    }
    if (i < MPROJ) {
        g_bc[i] = (i < 16) ? b1[i] : ((i < 32) ? b2[i - 16] : b3[i - 32]);
    }
}

// ---------------- kernel 1: projection GEMM -------------------------------
#define BM 96
#define BN 64
#define BK 16
__global__ __launch_bounds__(256) void proj_gemm(const float* __restrict__ x) {
    __shared__ float As[BK][BM + 1];
    __shared__ float Bs[BK][BN];

    int b  = blockIdx.z;
    int m0 = blockIdx.y * BM;
    int n0 = blockIdx.x * BN;
    int t  = threadIdx.x;
    int tx = t & 15;
    int ty = t >> 4;

    const float* xb = x + (size_t)b * CIN * HW;

    float acc[6][4];
#pragma unroll
    for (int i = 0; i < 6; i++)
#pragma unroll
        for (int j = 0; j < 4; j++) acc[i][j] = 0.0f;

    for (int k0 = 0; k0 < CIN; k0 += BK) {
#pragma unroll
        for (int q = 0; q < 6; q++) {
            int idx = t + q * 256;
            int col = idx & 15;
            int row = idx >> 4;
            As[col][row] = g_wc[(m0 + row) * CIN + k0 + col];
        }
        {
            int row = t >> 4, cg = t & 15;
            float4 v = *reinterpret_cast<const float4*>(&xb[(size_t)(k0 + row) * HW + n0 + cg * 4]);
            *reinterpret_cast<float4*>(&Bs[row][cg * 4]) = v;
        }
        __syncthreads();
#pragma unroll
        for (int k = 0; k < BK; k++) {
            float a[6];
#pragma unroll
            for (int i = 0; i < 6; i++) a[i] = As[k][ty * 6 + i];
            float4 bv = *reinterpret_cast<float4*>(&Bs[k][tx * 4]);
            float bb[4] = {bv.x, bv.y, bv.z, bv.w};
#pragma unroll
            for (int i = 0; i < 6; i++)
#pragma unroll
                for (int j = 0; j < 4; j++) acc[i][j] = fmaf(a[i], bb[j], acc[i][j]);
        }
        __syncthreads();
    }
#pragma unroll
    for (int i = 0; i < 6; i++) {
        int m = m0 + ty * 6 + i;
        float bias = g_bc[m];
        float4 v = make_float4(acc[i][0] + bias, acc[i][1] + bias,
                               acc[i][2] + bias, acc[i][3] + bias);
        *reinterpret_cast<float4*>(&g_proj[((size_t)b * MPROJ + m) * HW + n0 + tx * 4]) = v;
    }
}

// ---------------- kernel 2: attention weights + softmax -------------------
// 224 threads; thread = (pixel 0..3, tap 0..48); 4 consecutive pixels (same row).
#define APX 4
__global__ __launch_bounds__(224) void attn_kernel(
    const float* __restrict__ bn1g, const float* __restrict__ bn1b,
    const float* __restrict__ bn1m, const float* __restrict__ bn1v,
    const float* __restrict__ cw1,
    const float* __restrict__ bn2g, const float* __restrict__ bn2b,
    const float* __restrict__ bn2m, const float* __restrict__ bn2v,
    const float* __restrict__ cw2, const float* __restrict__ cb) {

    __shared__ float s_logit[APX][32][49];   // 25.1 KB
    __shared__ float sx2[16 * 72];           // x2 region: 7 rows x 10 cols, stride 72
    __shared__ float sx1[16][APX];
    __shared__ float s1[16], t1[16], s2[16], t2[16];
    __shared__ float scw1[256], scw2[512], scb[32];
    __shared__ float smax[APX][32], sinv[APX][32];

    int t = threadIdx.x;
    int b = blockIdx.y;
    int p0 = blockIdx.x * APX;     // 4 consecutive pixels, always same row
    int h = p0 / W_, w0 = p0 % W_;

    if (t < 16) {
        float s = bn1g[t] * rsqrtf(bn1v[t] + 1e-5f);
        s1[t] = s; t1[t] = bn1b[t] - s * bn1m[t];
        float ss = bn2g[t] * rsqrtf(bn2v[t] + 1e-5f);
        s2[t] = ss; t2[t] = bn2b[t] - ss * bn2m[t];
    }
    for (int i = t; i < 256; i += 224) scw1[i] = cw1[i];
    for (int i = t; i < 512; i += 224) scw2[i] = cw2[i];
    if (t < 32) scb[t] = cb[t];

    const float* base = g_proj + (size_t)b * MPROJ * HW;
    if (t < 64) {
        int c = t >> 2, px = t & 3;
        sx1[c][px] = base[c * HW + p0 + px];
    }
    // x2 region rows h-3..h+3, cols w0-3..w0+6  (16 ch x 70)
    for (int i = t; i < 16 * 70; i += 224) {
        int c = i / 70, rem = i % 70, rr = rem / 10, cc = rem % 10;
        int gh = refl(h + rr - 3, H_), gw = refl(w0 + cc - 3, W_);
        sx2[c * 72 + rr * 10 + cc] = base[(size_t)(16 + c) * HW + gh * W_ + gw];
    }
    __syncthreads();

    if (t < APX * 49) {
        int pix = t / 49, k = t % 49;
        int dy = k / 7, dx = k % 7;
        const float* xs = sx2 + dy * 10 + (pix + dx);
        float h1[16];
#pragma unroll
        for (int o = 0; o < 16; o++) h1[o] = 0.0f;
#pragma unroll
        for (int c = 0; c < 16; c++) {
            float d = sx1[c][pix] - xs[c * 72];
            float a = fmaxf(fmaf(s1[c], d, t1[c]), 0.0f);
#pragma unroll
            for (int o = 0; o < 16; o++) h1[o] = fmaf(scw1[o * 16 + c], a, h1[o]);
        }
        float h2[32];
#pragma unroll
        for (int g = 0; g < 32; g++) h2[g] = scb[g];
#pragma unroll
        for (int o = 0; o < 16; o++) {
            float a = fmaxf(fmaf(s2[o], h1[o], t2[o]), 0.0f);
#pragma unroll
            for (int g = 0; g < 32; g++) h2[g] = fmaf(scw2[g * 16 + o], a, h2[g]);
        }
#pragma unroll
        for (int g = 0; g < 32; g++) s_logit[pix][g][k] = h2[g];
    }
    __syncthreads();

    if (t < APX * 32) {
        int pix = t >> 5, g = t & 31;
        float m = -1e30f;
#pragma unroll
        for (int k = 0; k < 49; k++) m = fmaxf(m, s_logit[pix][g][k]);
        float s = 0.0f;
#pragma unroll
        for (int k = 0; k < 49; k++) s += __expf(s_logit[pix][g][k] - m);
        smax[pix][g] = m;
        sinv[pix][g] = 1.0f / s;
    }
    __syncthreads();

    // write g_w[b][g][p0..p0+3][k]: contiguous 196-float runs per g
    const size_t gbase = ((size_t)b * WS_) * HW * K2 + (size_t)p0 * K2;
    for (int flat = t; flat < APX * 32 * 49; flat += 224) {
        int g = flat / 196, off = flat % 196;
        int pix = off / 49, k = off % 49;
        float v = __expf(s_logit[pix][g][k] - smax[pix][g]) * sinv[pix][g];
        g_w[gbase + (size_t)g * HW * K2 + off] = v;
    }
}

// ---------------- kernel 3: aggregation (tiled, smem-staged) --------------
// grid (49 tiles, 32 g, 4 b); 256 threads; 8x8 pixel tile; x3 window in smem.
__global__ __launch_bounds__(256) void agg_kernel() {
    __shared__ float sw[64 * 49];        // [pl][k]  12.5 KB
    __shared__ float sx3[8 * 200];       // [s][rr*14+cc], stride 200 (200%32==8)

    int b = blockIdx.z, g = blockIdx.y, tile = blockIdx.x;
    int ty0 = (tile / 7) * 8, tx0 = (tile % 7) * 8;
    int t = threadIdx.x;

    // stage w: 8 pixel-runs of 392 floats (98 float4) each
    const float* wp = g_w + ((size_t)(b * WS_ + g)) * HW * K2;
    for (int i = t; i < 784; i += 256) {
        int run = i / 98, off = i % 98;
        int p = (ty0 + run) * W_ + tx0;
        reinterpret_cast<float4*>(sw)[run * 98 + off] =
            reinterpret_cast<const float4*>(wp + (size_t)p * K2)[off];
    }
    // stage x3: 8 channels x 14x14 window (reflect-padded)
    const float* x3b = g_proj + ((size_t)b * MPROJ + 32 + g * 8) * HW;
    for (int i = t; i < 8 * 196; i += 256) {
        int s = i / 196, rem = i % 196, rr = rem / 14, cc = rem % 14;
        int gh = refl(ty0 + rr - 3, H_), gw = refl(tx0 + cc - 3, W_);
        sx3[s * 200 + rem] = x3b[(size_t)s * HW + gh * W_ + gw];
    }
    __syncthreads();

    int lane = t & 31, warp = t >> 5;
    int ls = lane >> 3, lp = lane & 7;   // s-quarter, pixel col
    int pr = warp, pc = lp;              // pixel row/col in tile
    int pl = pr * 8 + pc;

    const float* wsp = sw + pl * 49;
    const float* a0 = sx3 + ls * 200 + pr * 14 + pc;
    const float* a1 = a0 + 4 * 200;
    float acc0 = 0.0f, acc1 = 0.0f;
#pragma unroll
    for (int i = 0; i < 7; i++)
#pragma unroll
        for (int j = 0; j < 7; j++) {
            float wv = wsp[i * 7 + j];
            acc0 = fmaf(a0[i * 14 + j], wv, acc0);
            acc1 = fmaf(a1[i * 14 + j], wv, acc1);
        }
    int p = (ty0 + pr) * W_ + tx0 + pc;
    g_agg[((size_t)b * OUT_ + g * 8 + ls) * HW + p] = acc0;
    g_agg[((size_t)b * OUT_ + g * 8 + ls + 4) * HW + p] = acc1;
}

// ---------------- kernel 4: position2 grouped conv ------------------------
__global__ __launch_bounds__(256) void pos2_kernel(const float* __restrict__ pos2w,
                                                   float* __restrict__ out) {
    __shared__ float sw[64 * 49];
    __shared__ float sxv[8][64];
    __shared__ float spw[8 * 57];

    int b = blockIdx.z, g = blockIdx.y, p0 = blockIdx.x * 64;
    int t = threadIdx.x;

    const float* wp = g_w + (((size_t)b * WS_ + g) * HW + p0) * K2;
    for (int i = t; i < 64 * 49 / 4; i += 256)
        reinterpret_cast<float4*>(sw)[i] = reinterpret_cast<const float4*>(wp)[i];
    for (int i = t; i < 8 * 57; i += 256) spw[i] = pos2w[g * 8 * 57 + i];
    for (int i = t; i < 512; i += 256) {
        int s = i >> 6, pl = i & 63;
        sxv[s][pl] = g_agg[((size_t)b * OUT_ + s * 32 + g) * HW + p0 + pl];
    }
    __syncthreads();

    int pl = t & 63, oq = t >> 6;
    const float* wsm = sw + pl * 49;
#pragma unroll
    for (int oi = 0; oi < 2; oi++) {
        int o = oq + oi * 4;
        float acc = 0.0f;
#pragma unroll
        for (int s = 0; s < 8; s++) acc = fmaf(sxv[s][pl], spw[o * 57 + s], acc);
#pragma unroll
        for (int k = 0; k < 49; k++) acc = fmaf(wsm[k], spw[o * 57 + 8 + k], acc);
        out[((size_t)b * OUT_ + g * 8 + o) * HW + p0 + pl] = acc;
    }
}

// ---------------- launch ---------------------------------------------------
extern "C" void kernel_launch(void* const* d_in, const int* in_sizes, int n_in,
                              void* d_out, int out_size) {
    const float* x    = (const float*)d_in[0];
    const float* w1   = (const float*)d_in[1];
    const float* b1   = (const float*)d_in[2];
    const float* w2   = (const float*)d_in[3];
    const float* b2   = (const float*)d_in[4];
    const float* w3   = (const float*)d_in[5];
    const float* b3   = (const float*)d_in[6];
    const float* bn1g = (const float*)d_in[7];
    const float* bn1b = (const float*)d_in[8];
    const float* bn1m = (const float*)d_in[9];
    const float* bn1v = (const float*)d_in[10];
    const float* cw1  = (const float*)d_in[11];
    const float* bn2g = (const float*)d_in[12];
    const float* bn2b = (const float*)d_in[13];
    const float* bn2m = (const float*)d_in[14];
    const float* bn2v = (const float*)d_in[15];
    const float* cw2  = (const float*)d_in[16];
    const float* cb   = (const float*)d_in[17];
    const float* p2w  = (const float*)d_in[18];
    float* out = (float*)d_out;

    pack_kernel<<<(MPROJ * CIN + 255) / 256, 256>>>(w1, b1, w2, b2, w3, b3);

    dim3 gg(HW / BN, MPROJ / BM, B_);
    proj_gemm<<<gg, 256>>>(x);

    attn_kernel<<<dim3(HW / APX, B_), 224>>>(bn1g, bn1b, bn1m, bn1v, cw1,
                                             bn2g, bn2b, bn2m, bn2v, cw2, cb);

    dim3 ga(49, WS_, B_);
    agg_kernel<<<ga, 256>>>();

    dim3 gp(HW / 64, WS_, B_);
    pos2_kernel<<<gp, 256>>>(p2w, out);
}

// round 3
// speedup vs baseline: 3.7811x; 1.2728x over previous
#include <cuda_runtime.h>

// ---------------- problem constants ----------------
#define B_    4
#define CIN   256
#define H_    56
#define W_    56
#define HW    3136
#define REL   16
#define OUT_  256
#define SP_   8
#define WS_   32
#define K2    49
#define KP    52            // padded taps (16B-aligned rows in g_w)
#define MPROJ 288

// ---------------- scratch (device globals) --------------------------------
__device__ float g_wc[MPROJ * CIN];
__device__ float g_bc[MPROJ];
__device__ float g_proj[B_ * MPROJ * HW];
__device__ float g_w[B_ * WS_ * HW * KP];    // [b][g][p][52], k>=49 zero
__device__ float g_agg[B_ * OUT_ * HW];

__device__ __forceinline__ int refl(int i, int n) {
    if (i < 0) i = -i;
    if (i >= n) i = 2 * n - 2 - i;
    return i;
}

// ---------------- kernel 0: pack projection weights -----------------------
__global__ void pack_kernel(const float* __restrict__ w1, const float* __restrict__ b1,
                            const float* __restrict__ w2, const float* __restrict__ b2,
                            const float* __restrict__ w3, const float* __restrict__ b3) {
    int i = blockIdx.x * blockDim.x + threadIdx.x;
    if (i < MPROJ * CIN) {
        int r = i / CIN, c = i % CIN;
        float v;
        if (r < 16)      v = w1[r * CIN + c];
        else if (r < 32) v = w2[(r - 16) * CIN + c];
        else             v = w3[(r - 32) * CIN + c];
        g_wc[i] = v;
    }
    if (i < MPROJ) {
        g_bc[i] = (i < 16) ? b1[i] : ((i < 32) ? b2[i - 16] : b3[i - 32]);
    }
}

// ---------------- kernel 1: projection GEMM -------------------------------
#define BM 96
#define BN 64
#define BK 16
__global__ __launch_bounds__(256) void proj_gemm(const float* __restrict__ x) {
    __shared__ float As[BK][BM + 1];
    __shared__ __align__(16) float Bs[BK][BN];

    int b  = blockIdx.z;
    int m0 = blockIdx.y * BM;
    int n0 = blockIdx.x * BN;
    int t  = threadIdx.x;
    int tx = t & 15;
    int ty = t >> 4;

    const float* xb = x + (size_t)b * CIN * HW;

    float acc[6][4];
#pragma unroll
    for (int i = 0; i < 6; i++)
#pragma unroll
        for (int j = 0; j < 4; j++) acc[i][j] = 0.0f;

    for (int k0 = 0; k0 < CIN; k0 += BK) {
#pragma unroll
        for (int q = 0; q < 6; q++) {
            int idx = t + q * 256;
            int col = idx & 15;
            int row = idx >> 4;
            As[col][row] = g_wc[(m0 + row) * CIN + k0 + col];
        }
        {
            int row = t >> 4, cg = t & 15;
            float4 v = *reinterpret_cast<const float4*>(&xb[(size_t)(k0 + row) * HW + n0 + cg * 4]);
            *reinterpret_cast<float4*>(&Bs[row][cg * 4]) = v;
        }
        __syncthreads();
#pragma unroll
        for (int k = 0; k < BK; k++) {
            float a[6];
#pragma unroll
            for (int i = 0; i < 6; i++) a[i] = As[k][ty * 6 + i];
            float4 bv = *reinterpret_cast<float4*>(&Bs[k][tx * 4]);
            float bb[4] = {bv.x, bv.y, bv.z, bv.w};
#pragma unroll
            for (int i = 0; i < 6; i++)
#pragma unroll
                for (int j = 0; j < 4; j++) acc[i][j] = fmaf(a[i], bb[j], acc[i][j]);
        }
        __syncthreads();
    }
#pragma unroll
    for (int i = 0; i < 6; i++) {
        int m = m0 + ty * 6 + i;
        float bias = g_bc[m];
        float4 v = make_float4(acc[i][0] + bias, acc[i][1] + bias,
                               acc[i][2] + bias, acc[i][3] + bias);
        *reinterpret_cast<float4*>(&g_proj[((size_t)b * MPROJ + m) * HW + n0 + tx * 4]) = v;
    }
}

// ---------------- kernel 2: attention weights + softmax -------------------
#define APX 4
__global__ __launch_bounds__(224) void attn_kernel(
    const float* __restrict__ bn1g, const float* __restrict__ bn1b,
    const float* __restrict__ bn1m, const float* __restrict__ bn1v,
    const float* __restrict__ cw1,
    const float* __restrict__ bn2g, const float* __restrict__ bn2b,
    const float* __restrict__ bn2m, const float* __restrict__ bn2v,
    const float* __restrict__ cw2, const float* __restrict__ cb) {

    __shared__ float s_logit[APX * 32 * 49];      // 25.1 KB (holds exp after stats)
    __shared__ float sx2[16 * 72];
    __shared__ float sx1[16][APX];
    __shared__ float s1[16], t1[16], s2[16], t2[16];
    __shared__ __align__(16) float scw1t[256];    // [c][o]
    __shared__ __align__(16) float scw2t[512];    // [o][g]
    __shared__ float scb[32];
    __shared__ float sinv[APX][32];

    int t = threadIdx.x;
    int b = blockIdx.y;
    int p0 = blockIdx.x * APX;        // 4 consecutive pixels, same row
    int h = p0 / W_, w0 = p0 % W_;

    if (t < 16) {
        float s = bn1g[t] * rsqrtf(bn1v[t] + 1e-5f);
        s1[t] = s; t1[t] = bn1b[t] - s * bn1m[t];
        float ss = bn2g[t] * rsqrtf(bn2v[t] + 1e-5f);
        s2[t] = ss; t2[t] = bn2b[t] - ss * bn2m[t];
    }
    for (int i = t; i < 256; i += 224) { int c = i >> 4, o = i & 15; scw1t[i] = cw1[o * 16 + c]; }
    for (int i = t; i < 512; i += 224) { int o = i >> 5, g = i & 31; scw2t[i] = cw2[g * 16 + o]; }
    if (t < 32) scb[t] = cb[t];

    const float* base = g_proj + (size_t)b * MPROJ * HW;
    if (t >= 128 && t < 192) {
        int idx = t - 128;
        int c = idx >> 2, px = idx & 3;
        sx1[c][px] = base[c * HW + p0 + px];
    }
    for (int i = t; i < 16 * 70; i += 224) {
        int c = i / 70, rem = i % 70, rr = rem / 10, cc = rem % 10;
        int gh = refl(h + rr - 3, H_), gw = refl(w0 + cc - 3, W_);
        sx2[c * 72 + rr * 10 + cc] = base[(size_t)(16 + c) * HW + gh * W_ + gw];
    }
    __syncthreads();

    if (t < APX * 49) {
        int pix = t / 49, k = t % 49;
        int dy = k / 7, dx = k % 7;
        const float* xs = sx2 + dy * 10 + dx + pix;
        float h1[16];
#pragma unroll
        for (int o = 0; o < 16; o++) h1[o] = 0.0f;
#pragma unroll
        for (int c = 0; c < 16; c++) {
            float d = sx1[c][pix] - xs[c * 72];
            float a = fmaxf(fmaf(s1[c], d, t1[c]), 0.0f);
            const float4* wrow = reinterpret_cast<const float4*>(scw1t + c * 16);
#pragma unroll
            for (int q = 0; q < 4; q++) {
                float4 wq = wrow[q];
                h1[q * 4 + 0] = fmaf(a, wq.x, h1[q * 4 + 0]);
                h1[q * 4 + 1] = fmaf(a, wq.y, h1[q * 4 + 1]);
                h1[q * 4 + 2] = fmaf(a, wq.z, h1[q * 4 + 2]);
                h1[q * 4 + 3] = fmaf(a, wq.w, h1[q * 4 + 3]);
            }
        }
        float h2[32];
#pragma unroll
        for (int g = 0; g < 32; g++) h2[g] = scb[g];
#pragma unroll
        for (int o = 0; o < 16; o++) {
            float a = fmaxf(fmaf(s2[o], h1[o], t2[o]), 0.0f);
            const float4* wrow = reinterpret_cast<const float4*>(scw2t + o * 32);
#pragma unroll
            for (int q = 0; q < 8; q++) {
                float4 wq = wrow[q];
                h2[q * 4 + 0] = fmaf(a, wq.x, h2[q * 4 + 0]);
                h2[q * 4 + 1] = fmaf(a, wq.y, h2[q * 4 + 1]);
                h2[q * 4 + 2] = fmaf(a, wq.z, h2[q * 4 + 2]);
                h2[q * 4 + 3] = fmaf(a, wq.w, h2[q * 4 + 3]);
            }
        }
#pragma unroll
        for (int g = 0; g < 32; g++) s_logit[pix * 1568 + g * 49 + k] = h2[g];
    }
    __syncthreads();

    // softmax: compute exp in place, keep 1/sum
    if (t < APX * 32) {
        int pix = t >> 5, g = t & 31;
        float* row = s_logit + pix * 1568 + g * 49;
        float m = row[0];
#pragma unroll
        for (int k = 1; k < 49; k++) m = fmaxf(m, row[k]);
        float s = 0.0f;
#pragma unroll
        for (int k = 0; k < 49; k++) {
            float e = __expf(row[k] - m);
            row[k] = e;
            s += e;
        }
        sinv[pix][g] = 1.0f / s;
    }
    __syncthreads();

    // write g_w[b][g][p][52] (pads zeroed), coalesced runs
    for (int flat = t; flat < 32 * APX * KP; flat += 224) {
        int g = flat / (APX * KP);
        int rem = flat % (APX * KP);
        int pix = rem / KP, k = rem % KP;
        float v = 0.0f;
        if (k < 49) v = s_logit[pix * 1568 + g * 49 + k] * sinv[pix][g];
        g_w[((size_t)(b * WS_ + g) * HW + p0 + pix) * KP + k] = v;
    }
}

// ---------------- kernel 3: aggregation -----------------------------------
// 128 threads: pl=pixel(64), sq=channel-quad(2); x3 s-fastest stride 12.
__global__ __launch_bounds__(128) void agg_kernel() {
    __shared__ __align__(16) float sw[64 * KP];     // 13.3 KB
    __shared__ __align__(16) float sx3[196 * 12];   // 9.4 KB

    int b = blockIdx.z, g = blockIdx.y, tile = blockIdx.x;
    int ty0 = (tile / 7) * 8, tx0 = (tile % 7) * 8;
    int t = threadIdx.x;

    const float4* wp4 = reinterpret_cast<const float4*>(
        g_w + (size_t)(b * WS_ + g) * HW * KP);
    for (int i = t; i < 832; i += 128) {
        int run = i / 104, off = i % 104;
        int prow = (ty0 + run) * W_ + tx0;
        reinterpret_cast<float4*>(sw)[run * 104 + off] = wp4[prow * 13 + off];
    }
    const float* x3b = g_proj + ((size_t)b * MPROJ + 32 + g * 8) * HW;
    for (int i = t; i < 1568; i += 128) {
        int s = i / 196, rem = i % 196;
        int rr = rem / 14, cc = rem % 14;
        int gh = refl(ty0 + rr - 3, H_), gw = refl(tx0 + cc - 3, W_);
        sx3[rem * 12 + s] = x3b[(size_t)s * HW + gh * W_ + gw];
    }
    __syncthreads();

    int pl = t & 63, sq = t >> 6;
    int pr = pl >> 3, pc = pl & 7;
    const float4* w4 = reinterpret_cast<const float4*>(sw + pl * KP);
    const float4* x4 = reinterpret_cast<const float4*>(sx3) + (pr * 14 + pc) * 3 + sq;

    float a0 = 0.f, a1 = 0.f, a2 = 0.f, a3 = 0.f;
#pragma unroll
    for (int k4 = 0; k4 < 13; k4++) {
        float4 wv = w4[k4];
        float wk[4] = {wv.x, wv.y, wv.z, wv.w};
#pragma unroll
        for (int u = 0; u < 4; u++) {
            int k = k4 * 4 + u;
            if (k < 49) {
                int i = k / 7, j = k % 7;
                float4 xv = x4[(i * 14 + j) * 3];
                a0 = fmaf(xv.x, wk[u], a0);
                a1 = fmaf(xv.y, wk[u], a1);
                a2 = fmaf(xv.z, wk[u], a2);
                a3 = fmaf(xv.w, wk[u], a3);
            }
        }
    }
    int p = (ty0 + pr) * W_ + tx0 + pc;
    float* dst = g_agg + ((size_t)b * OUT_ + g * 8 + sq * 4) * HW + p;
    dst[0] = a0; dst[HW] = a1; dst[2 * HW] = a2; dst[3 * HW] = a3;
}

// ---------------- kernel 4: position2 grouped conv ------------------------
// 64 threads: thread = pixel, computes all 8 outputs with float4 LDS.
__global__ __launch_bounds__(64) void pos2_kernel(const float* __restrict__ pos2w,
                                                  float* __restrict__ out) {
    __shared__ __align__(16) float sw[64 * KP];   // 13.3 KB
    __shared__ __align__(16) float spw[8 * 60];   // zero-padded
    __shared__ float sxv[8][64];

    int b = blockIdx.z, g = blockIdx.y, p0 = blockIdx.x * 64;
    int t = threadIdx.x;

    const float4* wp4 = reinterpret_cast<const float4*>(
        g_w + ((size_t)(b * WS_ + g) * HW + p0) * KP);
    for (int i = t; i < 832; i += 64)
        reinterpret_cast<float4*>(sw)[i] = wp4[i];
    for (int i = t; i < 480; i += 64) {
        int o = i / 60, q = i % 60;
        spw[i] = (q < 57) ? pos2w[(g * 8 + o) * 57 + q] : 0.0f;
    }
    for (int i = t; i < 512; i += 64) {
        int s = i >> 6, pl = i & 63;
        sxv[s][pl] = g_agg[((size_t)b * OUT_ + s * 32 + g) * HW + p0 + pl];
    }
    __syncthreads();

    float acc[8];
#pragma unroll
    for (int o = 0; o < 8; o++) acc[o] = 0.0f;
#pragma unroll
    for (int s = 0; s < 8; s++) {
        float xv = sxv[s][t];
#pragma unroll
        for (int o = 0; o < 8; o++) acc[o] = fmaf(xv, spw[o * 60 + s], acc[o]);
    }
    const float4* w4 = reinterpret_cast<const float4*>(sw + t * KP);
#pragma unroll
    for (int k4 = 0; k4 < 13; k4++) {
        float4 wv = w4[k4];
#pragma unroll
        for (int o = 0; o < 8; o++) {
            float4 pv = reinterpret_cast<const float4*>(spw + o * 60 + 8)[k4];
            acc[o] = fmaf(wv.x, pv.x, acc[o]);
            acc[o] = fmaf(wv.y, pv.y, acc[o]);
            acc[o] = fmaf(wv.z, pv.z, acc[o]);
            acc[o] = fmaf(wv.w, pv.w, acc[o]);
        }
    }
#pragma unroll
    for (int o = 0; o < 8; o++)
        out[((size_t)b * OUT_ + g * 8 + o) * HW + p0 + t] = acc[o];
}

// ---------------- launch ---------------------------------------------------
extern "C" void kernel_launch(void* const* d_in, const int* in_sizes, int n_in,
                              void* d_out, int out_size) {
    const float* x    = (const float*)d_in[0];
    const float* w1   = (const float*)d_in[1];
    const float* b1   = (const float*)d_in[2];
    const float* w2   = (const float*)d_in[3];
    const float* b2   = (const float*)d_in[4];
    const float* w3   = (const float*)d_in[5];
    const float* b3   = (const float*)d_in[6];
    const float* bn1g = (const float*)d_in[7];
    const float* bn1b = (const float*)d_in[8];
    const float* bn1m = (const float*)d_in[9];
    const float* bn1v = (const float*)d_in[10];
    const float* cw1  = (const float*)d_in[11];
    const float* bn2g = (const float*)d_in[12];
    const float* bn2b = (const float*)d_in[13];
    const float* bn2m = (const float*)d_in[14];
    const float* bn2v = (const float*)d_in[15];
    const float* cw2  = (const float*)d_in[16];
    const float* cb   = (const float*)d_in[17];
    const float* p2w  = (const float*)d_in[18];
    float* out = (float*)d_out;

    pack_kernel<<<(MPROJ * CIN + 255) / 256, 256>>>(w1, b1, w2, b2, w3, b3);

    dim3 gg(HW / BN, MPROJ / BM, B_);
    proj_gemm<<<gg, 256>>>(x);

    attn_kernel<<<dim3(HW / APX, B_), 224>>>(bn1g, bn1b, bn1m, bn1v, cw1,
                                             bn2g, bn2b, bn2m, bn2v, cw2, cb);

    dim3 ga(49, WS_, B_);
    agg_kernel<<<ga, 128>>>();
    pos2_kernel<<<ga, 64>>>(p2w, out);
}

// round 5
// speedup vs baseline: 5.0293x; 1.3301x over previous
#include <cuda_runtime.h>
#include <cuda_fp16.h>

// ---------------- problem constants ----------------
#define B_    4
#define CIN   256
#define H_    56
#define W_    56
#define HW    3136
#define OUT_  256
#define WS_   32
#define K2    49
#define KP    52            // padded taps (half2-friendly rows)
#define MPROJ 288
#define PC_   272           // padded channels: proj rows 16..287
#define PH    62
#define PW    64

// ---------------- scratch (device globals) --------------------------------
__device__ float  g_wc[MPROJ * CIN];
__device__ float  g_bc[MPROJ];
__device__ float  g_s1[16], g_t1[16];
__device__ float  g_proj[B_ * MPROJ * HW];
__device__ float  g_pad[(size_t)B_ * PC_ * PH * PW];     // reflect-padded ch 16..287
__device__ __half g_w[(size_t)B_ * WS_ * HW * KP];       // fp16 softmax weights
__device__ float  g_agg[B_ * OUT_ * HW];

__device__ __forceinline__ int refl(int i, int n) {
    if (i < 0) i = -i;
    if (i >= n) i = 2 * n - 2 - i;
    return i;
}

// ---------------- kernel 0: pack weights + bn1 fold -----------------------
__global__ void pack_kernel(const float* __restrict__ w1, const float* __restrict__ b1,
                            const float* __restrict__ w2, const float* __restrict__ b2,
                            const float* __restrict__ w3, const float* __restrict__ b3,
                            const float* __restrict__ bn1g, const float* __restrict__ bn1b,
                            const float* __restrict__ bn1m, const float* __restrict__ bn1v) {
    int i = blockIdx.x * blockDim.x + threadIdx.x;
    if (i < MPROJ * CIN) {
        int r = i / CIN, c = i % CIN;
        float v;
        if (r < 16)      v = w1[r * CIN + c];
        else if (r < 32) v = w2[(r - 16) * CIN + c];
        else             v = w3[(r - 32) * CIN + c];
        g_wc[i] = v;
    }
    if (i < MPROJ) {
        g_bc[i] = (i < 16) ? b1[i] : ((i < 32) ? b2[i - 16] : b3[i - 32]);
    }
    if (i < 16) {
        float s = bn1g[i] * rsqrtf(bn1v[i] + 1e-5f);
        g_s1[i] = s;
        g_t1[i] = bn1b[i] - s * bn1m[i];
    }
}

// ---------------- kernel 1: projection GEMM (BN1-folded epilogue) ---------
#define BM 96
#define BN 64
#define BK 16
__global__ __launch_bounds__(256) void proj_gemm(const float* __restrict__ x) {
    __shared__ float As[BK][BM + 1];
    __shared__ __align__(16) float Bs[BK][BN];

    int b  = blockIdx.z;
    int m0 = blockIdx.y * BM;
    int n0 = blockIdx.x * BN;
    int t  = threadIdx.x;
    int tx = t & 15;
    int ty = t >> 4;

    const float* xb = x + (size_t)b * CIN * HW;

    float acc[6][4];
#pragma unroll
    for (int i = 0; i < 6; i++)
#pragma unroll
        for (int j = 0; j < 4; j++) acc[i][j] = 0.0f;

    for (int k0 = 0; k0 < CIN; k0 += BK) {
#pragma unroll
        for (int q = 0; q < 6; q++) {
            int idx = t + q * 256;
            int col = idx & 15;
            int row = idx >> 4;
            As[col][row] = g_wc[(m0 + row) * CIN + k0 + col];
        }
        {
            int row = t >> 4, cg = t & 15;
            float4 v = *reinterpret_cast<const float4*>(&xb[(size_t)(k0 + row) * HW + n0 + cg * 4]);
            *reinterpret_cast<float4*>(&Bs[row][cg * 4]) = v;
        }
        __syncthreads();
#pragma unroll
        for (int k = 0; k < BK; k++) {
            float a[6];
#pragma unroll
            for (int i = 0; i < 6; i++) a[i] = As[k][ty * 6 + i];
            float4 bv = *reinterpret_cast<float4*>(&Bs[k][tx * 4]);
            float bb[4] = {bv.x, bv.y, bv.z, bv.w};
#pragma unroll
            for (int i = 0; i < 6; i++)
#pragma unroll
                for (int j = 0; j < 4; j++) acc[i][j] = fmaf(a[i], bb[j], acc[i][j]);
        }
        __syncthreads();
    }
#pragma unroll
    for (int i = 0; i < 6; i++) {
        int m = m0 + ty * 6 + i;
        float bias = g_bc[m];
        float vv[4];
#pragma unroll
        for (int j = 0; j < 4; j++) vv[j] = acc[i][j] + bias;
        if (m < 16) {
            float s = g_s1[m], tt = g_t1[m];
#pragma unroll
            for (int j = 0; j < 4; j++) vv[j] = fmaf(s, vv[j], tt);
        } else if (m < 32) {
            float s = g_s1[m - 16];
#pragma unroll
            for (int j = 0; j < 4; j++) vv[j] *= s;
        }
        float4 v = make_float4(vv[0], vv[1], vv[2], vv[3]);
        *reinterpret_cast<float4*>(&g_proj[((size_t)b * MPROJ + m) * HW + n0 + tx * 4]) = v;
    }
}

// ---------------- kernel 1b: reflect-pad channels 16..287 -----------------
__global__ void pad_kernel() {
    int idx = blockIdx.x * 256 + threadIdx.x;
    const int total = B_ * PC_ * PH * PW;
    if (idx >= total) return;
    int col = idx & 63;
    int rest = idx >> 6;
    int r = rest % PH;
    int cb = rest / PH;
    int c = cb % PC_;
    int b = cb / PC_;
    int oy = refl(r - 3, H_), ox = refl(col - 3, W_);
    g_pad[idx] = g_proj[((size_t)(b * MPROJ + 16 + c)) * HW + oy * W_ + ox];
}

// ---------------- kernel 2: attention weights + softmax (phase-split) -----
__global__ __launch_bounds__(224) void attn_kernel(
    const float* __restrict__ cw1,
    const float* __restrict__ bn2g, const float* __restrict__ bn2b,
    const float* __restrict__ bn2m, const float* __restrict__ bn2v,
    const float* __restrict__ cw2, const float* __restrict__ cb) {

    __shared__ __align__(16) float sx2[16 * 84];     // [c][dy*12 + (dx+pix)]
    __shared__ float sx1[64];                        // [pix*16 + c]  (BN1-folded)
    __shared__ __align__(16) float act0[196 * 16];   // stage1 acts -> stage2 acts (in place)
    __shared__ __align__(4) __half slog[4 * 32 * 52];// logits -> exp (fp16)
    __shared__ float s2s[16], t2s[16];
    __shared__ __align__(8) float scw1t[256];        // [c][o]
    __shared__ __align__(8) float scw2t[512];        // [o][g]
    __shared__ float scb[32];
    __shared__ float sinv[128];                      // [pix*32+g]

    int t = threadIdx.x;
    int b = blockIdx.y;
    int p0 = blockIdx.x * 4;          // 4 consecutive pixels, same row
    int h = p0 / W_, w0 = p0 % W_;

    if (t < 16) {
        float ss = bn2g[t] * rsqrtf(bn2v[t] + 1e-5f);
        s2s[t] = ss; t2s[t] = bn2b[t] - ss * bn2m[t];
    }
    for (int i = t; i < 256; i += 224) scw1t[i] = cw1[(i & 15) * 16 + (i >> 4)];
    for (int i = t; i < 512; i += 224) scw2t[i] = cw2[(i & 31) * 16 + (i >> 5)];
    if (t < 32) scb[t] = cb[t];
    if (t < 64) {
        int pix = t >> 4, c = t & 15;
        sx1[t] = g_proj[((size_t)b * MPROJ + c) * HW + p0 + pix];
    }
    // x2' window from g_pad: rows h..h+6, cols w0..w0+11 (pad idx, ch 0..15)
    const float* padb = g_pad + (size_t)b * PC_ * PH * PW;
    for (int i = t; i < 336; i += 224) {
        int c = i / 21, rem = i % 21, dy = rem / 3, cg = rem % 3;
        float4 v = *reinterpret_cast<const float4*>(
            padb + ((size_t)c * PH + h + dy) * PW + w0 + cg * 4);
        *reinterpret_cast<float4*>(sx2 + c * 84 + dy * 12 + cg * 4) = v;
    }
    __syncthreads();

    // phase1: stage1 activation relu(x1' - x2')
    if (t < 196) {
        int pix = t / 49, k = t % 49;
        int dy = k / 7, dx = k % 7;
        const float* x2p = sx2 + dy * 12 + dx + pix;
        const float* x1p = sx1 + pix * 16;
        float av[16];
#pragma unroll
        for (int c = 0; c < 16; c++) av[c] = fmaxf(x1p[c] - x2p[c * 84], 0.0f);
        float4* dst = reinterpret_cast<float4*>(act0 + t * 16);
#pragma unroll
        for (int q = 0; q < 4; q++)
            dst[q] = make_float4(av[q * 4], av[q * 4 + 1], av[q * 4 + 2], av[q * 4 + 3]);
    }
    __syncthreads();

    // phase2: GEMM1 (16->16) + BN2 + ReLU, in place. thread = (o-pair, pt-stride)
    {
        int op = t & 7, pb = t >> 3;
        int o0 = op * 2;
        float2 w1r[16];
#pragma unroll
        for (int c = 0; c < 16; c++)
            w1r[c] = *reinterpret_cast<const float2*>(scw1t + c * 16 + o0);
        float s2a = s2s[o0], s2b = s2s[o0 + 1];
        float t2a = t2s[o0], t2b = t2s[o0 + 1];
#pragma unroll
        for (int n = 0; n < 7; n++) {
            int pt = pb + 28 * n;
            const float4* ap = reinterpret_cast<const float4*>(act0 + pt * 16);
            float a[16];
            *reinterpret_cast<float4*>(a + 0)  = ap[0];
            *reinterpret_cast<float4*>(a + 4)  = ap[1];
            *reinterpret_cast<float4*>(a + 8)  = ap[2];
            *reinterpret_cast<float4*>(a + 12) = ap[3];
            float h0 = 0.0f, h1 = 0.0f;
#pragma unroll
            for (int c = 0; c < 16; c++) {
                h0 = fmaf(a[c], w1r[c].x, h0);
                h1 = fmaf(a[c], w1r[c].y, h1);
            }
            __syncwarp();
            float r0 = fmaxf(fmaf(s2a, h0, t2a), 0.0f);
            float r1 = fmaxf(fmaf(s2b, h1, t2b), 0.0f);
            *reinterpret_cast<float2*>(act0 + pt * 16 + o0) = make_float2(r0, r1);
            __syncwarp();
        }
    }
    __syncthreads();

    // phase3: GEMM2 (16->32) + bias -> fp16 logits. thread = (g-pair, pt-stride)
    {
        int gp = t & 15, pb = t >> 4;
        int g0 = gp * 2;
        float2 w2r[16];
#pragma unroll
        for (int o = 0; o < 16; o++)
            w2r[o] = *reinterpret_cast<const float2*>(scw2t + o * 32 + g0);
        float bias0 = scb[g0], bias1 = scb[g0 + 1];
#pragma unroll
        for (int n = 0; n < 14; n++) {
            int pt = pb + 14 * n;
            const float4* ap = reinterpret_cast<const float4*>(act0 + pt * 16);
            float a[16];
            *reinterpret_cast<float4*>(a + 0)  = ap[0];
            *reinterpret_cast<float4*>(a + 4)  = ap[1];
            *reinterpret_cast<float4*>(a + 8)  = ap[2];
            *reinterpret_cast<float4*>(a + 12) = ap[3];
            float h0 = bias0, h1 = bias1;
#pragma unroll
            for (int o = 0; o < 16; o++) {
                h0 = fmaf(a[o], w2r[o].x, h0);
                h1 = fmaf(a[o], w2r[o].y, h1);
            }
            int pix = pt / 49, k = pt - pix * 49;
            slog[(pix * 32 + g0) * 52 + k]     = __float2half(h0);
            slog[(pix * 32 + g0 + 1) * 52 + k] = __float2half(h1);
        }
    }
    __syncthreads();

    // phase4: softmax over 49 taps; store exp (fp16) back, keep 1/sum
    if (t < 128) {
        __half2* row = reinterpret_cast<__half2*>(slog) + t * 26;
        float m = -1e30f;
#pragma unroll
        for (int k2 = 0; k2 < 24; k2++) {
            float2 f = __half22float2(row[k2]);
            m = fmaxf(m, fmaxf(f.x, f.y));
        }
        m = fmaxf(m, __half22float2(row[24]).x);   // tap 48
        float s = 0.0f;
#pragma unroll
        for (int k2 = 0; k2 < 24; k2++) {
            float2 f = __half22float2(row[k2]);
            float ex = __expf(f.x - m), ey = __expf(f.y - m);
            s += ex + ey;
            row[k2] = __floats2half2_rn(ex, ey);
        }
        {
            float ex = __expf(__half22float2(row[24]).x - m);
            s += ex;
            row[24] = __floats2half2_rn(ex, 0.0f);
            row[25] = __floats2half2_rn(0.0f, 0.0f);
        }
        sinv[t] = 1.0f / s;
    }
    __syncthreads();

    // phase5: scale + write fp16 g_w[b][g][p][52]
    __half2* gw2 = reinterpret_cast<__half2*>(g_w);
    const __half2* sl2 = reinterpret_cast<const __half2*>(slog);
    for (int i = t; i < 3328; i += 224) {
        int g = i / 104, rem = i - g * 104;
        int pix = rem / 26, k2 = rem - pix * 26;
        float2 f = __half22float2(sl2[(pix * 32 + g) * 26 + k2]);
        float inv = sinv[pix * 32 + g];
        gw2[(((size_t)(b * WS_ + g)) * HW + p0 + pix) * 26 + k2] =
            __floats2half2_rn(f.x * inv, f.y * inv);
    }
}

// ---------------- kernel 3: aggregation -----------------------------------
// 128 threads: pl=pixel(64), sq=ch-quad(2); x3 from g_pad, [c][row][24] smem.
__global__ __launch_bounds__(128) void agg_kernel() {
    __shared__ __align__(4) __half swh[64 * KP];     // 6.6 KB fp16 weights [pl][52]
    __shared__ __align__(16) float sx3[8 * 14 * 24]; // 10.5 KB  [c][r][24]

    int b = blockIdx.z, g = blockIdx.y, tile = blockIdx.x;
    int ty0 = (tile / 7) * 8, tx0 = (tile % 7) * 8;
    int t = threadIdx.x;

    const __half2* gw2 = reinterpret_cast<const __half2*>(g_w);
    size_t wbase = ((size_t)(b * WS_ + g)) * HW;
    for (int i = t; i < 1664; i += 128) {
        int run = i / 208, off = i - run * 208;
        reinterpret_cast<__half2*>(swh)[run * 208 + off] =
            gw2[(wbase + (ty0 + run) * W_ + tx0) * 26 + off];
    }
    const float* padb = g_pad + ((size_t)(b * PC_) + 16 + g * 8) * PH * PW;
    for (int i = t; i < 448; i += 128) {
        int c = i / 56, rem = i - c * 56, r = rem >> 2, cg = rem & 3;
        float4 v = *reinterpret_cast<const float4*>(
            padb + ((size_t)c * PH + ty0 + r) * PW + tx0 + cg * 4);
        *reinterpret_cast<float4*>(sx3 + (c * 14 + r) * 24 + cg * 4) = v;
    }
    __syncthreads();

    int pl = t & 63, sq = t >> 6;
    int pr = pl >> 3, pc = pl & 7;
    const __half2* wp = reinterpret_cast<const __half2*>(swh + pl * KP);
    const float* xb = sx3 + sq * 4 * 336 + pr * 24 + pc;

    float a0 = 0.f, a1 = 0.f, a2 = 0.f, a3 = 0.f;
#pragma unroll
    for (int k2 = 0; k2 < 25; k2++) {
        float2 wf = __half22float2(wp[k2]);
        {
            int k = 2 * k2;
            int xo = (k / 7) * 24 + (k % 7);
            a0 = fmaf(xb[xo],        wf.x, a0);
            a1 = fmaf(xb[336 + xo],  wf.x, a1);
            a2 = fmaf(xb[672 + xo],  wf.x, a2);
            a3 = fmaf(xb[1008 + xo], wf.x, a3);
        }
        if (2 * k2 + 1 < 49) {
            int k = 2 * k2 + 1;
            int xo = (k / 7) * 24 + (k % 7);
            a0 = fmaf(xb[xo],        wf.y, a0);
            a1 = fmaf(xb[336 + xo],  wf.y, a1);
            a2 = fmaf(xb[672 + xo],  wf.y, a2);
            a3 = fmaf(xb[1008 + xo], wf.y, a3);
        }
    }
    int p = (ty0 + pr) * W_ + tx0 + pc;
    float* dst = g_agg + ((size_t)b * OUT_ + g * 8 + sq * 4) * HW + p;
    dst[0] = a0; dst[HW] = a1; dst[2 * HW] = a2; dst[3 * HW] = a3;
}

// ---------------- kernel 4: position2 grouped conv ------------------------
__global__ __launch_bounds__(128) void pos2_kernel(const float* __restrict__ pos2w,
                                                   float* __restrict__ out) {
    __shared__ __align__(16) float sw[64 * KP];   // 13.3 KB fp32 (converted)
    __shared__ __align__(16) float spw[8 * 60];
    __shared__ float sxv[8 * 64];

    int b = blockIdx.z, g = blockIdx.y, p0 = blockIdx.x * 64;
    int t = threadIdx.x;

    const __half2* gw2 = reinterpret_cast<const __half2*>(g_w);
    size_t base2 = (((size_t)(b * WS_ + g)) * HW + p0) * 26;
    for (int i = t; i < 1664; i += 128) {      // FIX: was 832 (covered only 32/64 pixels)
        float2 f = __half22float2(gw2[base2 + i]);
        *reinterpret_cast<float2*>(sw + 2 * i) = f;
    }
    for (int i = t; i < 480; i += 128) {
        int o = i / 60, q = i - o * 60;
        spw[i] = (q < 57) ? pos2w[(g * 8 + o) * 57 + q] : 0.0f;
    }
    for (int i = t; i < 512; i += 128) {
        int s = i >> 6, pl = i & 63;
        sxv[i] = g_agg[((size_t)b * OUT_ + s * 32 + g) * HW + p0 + pl];
    }
    __syncthreads();

    int pl = t & 63, oh = t >> 6;      // oh: o = oh*4 .. oh*4+3
    float acc[4] = {0.f, 0.f, 0.f, 0.f};
#pragma unroll
    for (int s = 0; s < 8; s++) {
        float xv = sxv[s * 64 + pl];
#pragma unroll
        for (int j = 0; j < 4; j++)
            acc[j] = fmaf(xv, spw[(oh * 4 + j) * 60 + s], acc[j]);
    }
    const float4* w4 = reinterpret_cast<const float4*>(sw + pl * KP);
#pragma unroll
    for (int k4 = 0; k4 < 13; k4++) {
        float4 wv = w4[k4];
#pragma unroll
        for (int j = 0; j < 4; j++) {
            float4 pv = *reinterpret_cast<const float4*>(spw + (oh * 4 + j) * 60 + 8 + k4 * 4);
            acc[j] = fmaf(wv.x, pv.x, acc[j]);
            acc[j] = fmaf(wv.y, pv.y, acc[j]);
            acc[j] = fmaf(wv.z, pv.z, acc[j]);
            acc[j] = fmaf(wv.w, pv.w, acc[j]);
        }
    }
#pragma unroll
    for (int j = 0; j < 4; j++)
        out[((size_t)b * OUT_ + g * 8 + oh * 4 + j) * HW + p0 + pl] = acc[j];
}

// ---------------- launch ---------------------------------------------------
extern "C" void kernel_launch(void* const* d_in, const int* in_sizes, int n_in,
                              void* d_out, int out_size) {
    const float* x    = (const float*)d_in[0];
    const float* w1   = (const float*)d_in[1];
    const float* b1   = (const float*)d_in[2];
    const float* w2   = (const float*)d_in[3];
    const float* b2   = (const float*)d_in[4];
    const float* w3   = (const float*)d_in[5];
    const float* b3   = (const float*)d_in[6];
    const float* bn1g = (const float*)d_in[7];
    const float* bn1b = (const float*)d_in[8];
    const float* bn1m = (const float*)d_in[9];
    const float* bn1v = (const float*)d_in[10];
    const float* cw1  = (const float*)d_in[11];
    const float* bn2g = (const float*)d_in[12];
    const float* bn2b = (const float*)d_in[13];
    const float* bn2m = (const float*)d_in[14];
    const float* bn2v = (const float*)d_in[15];
    const float* cw2  = (const float*)d_in[16];
    const float* cb   = (const float*)d_in[17];
    const float* p2w  = (const float*)d_in[18];
    float* out = (float*)d_out;

    pack_kernel<<<(MPROJ * CIN + 255) / 256, 256>>>(w1, b1, w2, b2, w3, b3,
                                                    bn1g, bn1b, bn1m, bn1v);

    dim3 gg(HW / BN, MPROJ / BM, B_);
    proj_gemm<<<gg, 256>>>(x);

    const int pad_total = B_ * PC_ * PH * PW;
    pad_kernel<<<(pad_total + 255) / 256, 256>>>();

    attn_kernel<<<dim3(HW / 4, B_), 224>>>(cw1, bn2g, bn2b, bn2m, bn2v, cw2, cb);

    dim3 ga(49, WS_, B_);
    agg_kernel<<<ga, 128>>>();
    pos2_kernel<<<ga, 128>>>(p2w, out);
}